// round 16
// baseline (speedup 1.0000x reference)
#include <cuda_runtime.h>
#include <cstdint>

// Problem dims (fixed for this instance)
#define BQ 64
#define TQ 256
#define DQ 300
#define HQ 256      // hidden
#define KQ 37       // tags
#define MBQ (TQ*BQ) // 16384 rows (t*B + b)

typedef unsigned long long ull;

// ---------------- scratch (static device globals; no allocation) ----------------
__device__ float g_xgA[(size_t)MBQ * 1024];  // 64 MB (gate-interleaved [t][b][unit][gate])
__device__ float g_xgB[(size_t)MBQ * 1024];  // 64 MB
__device__ float g_h0 [(size_t)MBQ * 512];   // 32 MB
__device__ float g_h1 [(size_t)MBQ * 512];   // 32 MB
__device__ float g_em [(size_t)MBQ * KQ];    // 2.4 MB
__device__ float g_llh[BQ];
__device__ unsigned g_bar[4096];             // 128 per-CTA step flags, 128B apart

// ---------------- helpers ----------------
__device__ __forceinline__ float sigf(float x)   { return 1.0f / (1.0f + __expf(-x)); }
__device__ __forceinline__ float tanh_f(float x) { return 2.0f / (1.0f + __expf(-2.0f * x)) - 1.0f; }

__device__ __forceinline__ ull ffma2(ull a, ull b, ull c) {
    ull d;
    asm("fma.rn.f32x2 %0, %1, %2, %3;" : "=l"(d) : "l"(a), "l"(b), "l"(c));
    return d;
}
__device__ __forceinline__ ull pk2(float lo, float hi) {
    ull r;
    asm("mov.b64 %0, {%1, %2};" : "=l"(r) : "f"(lo), "f"(hi));
    return r;
}
__device__ __forceinline__ float2 unpk2(ull v) {
    float2 r;
    asm("mov.b64 {%0, %1}, %2;" : "=f"(r.x), "=f"(r.y) : "l"(v));
    return r;
}
__device__ __forceinline__ unsigned ldcg_u32(const unsigned* p) {
    unsigned v;
    asm volatile("ld.global.cg.u32 %0, [%1];" : "=r"(v) : "l"(p) : "memory");
    return v;
}
__device__ __forceinline__ unsigned ldacq_u32(const unsigned* p) {
    unsigned v;
    asm volatile("ld.acquire.gpu.global.u32 %0, [%1];" : "=r"(v) : "l"(p) : "memory");
    return v;
}

__global__ void reset_bar_kernel() {
    #pragma unroll
    for (int k = 0; k < 16; ++k) g_bar[threadIdx.x + k * 256] = 0u;
}

// ---------------- GEMM: C[M,P] = A(M,K) * Bw'(P,K)^T + bias' ----------------
// 128x128 tile, 16-k, 256 threads, 8x8 microtile via FFMA2, reg prefetch,
// double-buffered smem (ONE sync per k-tile).
// XGI: logical output column p maps to weight/bias row (p&3)*256 + (p>>2).
#define GBM 128
#define GBN 128
#define GBK 16

template <bool GATHER, bool XGI>
__global__ void __launch_bounds__(256)
gemm_nt_bias(const float* __restrict__ A, const int* __restrict__ textp,
             const float* __restrict__ Bw, const float* __restrict__ bias,
             float* __restrict__ C, int M, int N, int Kd, int lda)
{
    __shared__ float As[2][GBK * GBM];
    __shared__ float Bs[2][GBK * GBN];

    const int tid = threadIdx.x;
    const int m0  = blockIdx.y * GBM;
    const int n0  = blockIdx.x * GBN;
    const int tx  = tid & 15;
    const int ty  = tid >> 4;
    const int lrow = tid >> 1;
    const int lkv0 = (tid & 1) * 2;

    ull acc2[8][4];
    #pragma unroll
    for (int i = 0; i < 8; ++i)
        #pragma unroll
        for (int j = 0; j < 4; ++j) acc2[i][j] = 0ull;

    const float* arow_p;
    {
        const int m = m0 + lrow;
        if (GATHER) {
            const int bb = m & 63;
            const int tt = m >> 6;
            const int tok = textp[bb * TQ + tt];
            arow_p = A + (size_t)tok * lda;
        } else {
            arow_p = A + (size_t)m * lda;
        }
    }
    const int ncol = n0 + lrow;
    const int brow = XGI ? ((ncol & 3) * 256 + (ncol >> 2)) : ncol;
    const float* brow_p = Bw + (size_t)brow * Kd;
    const bool bvalid = ncol < N;

    const int Ktiles = (Kd + GBK - 1) / GBK;

    float4 cva[2], cvb[2], nva[2], nvb[2];
    #pragma unroll
    for (int q = 0; q < 2; ++q) {
        const int kg = (lkv0 + q) * 4;
        cva[q] = make_float4(0.f, 0.f, 0.f, 0.f);
        cvb[q] = make_float4(0.f, 0.f, 0.f, 0.f);
        if (kg + 3 < Kd) {
            cva[q] = *(const float4*)(arow_p + kg);
            if (bvalid) cvb[q] = *(const float4*)(brow_p + kg);
        }
    }

    for (int kt = 0; kt < Ktiles; ++kt) {
        const int pb = kt & 1;
        #pragma unroll
        for (int q = 0; q < 2; ++q) {
            const int kv = lkv0 + q;
            As[pb][(kv * 4 + 0) * GBM + lrow] = cva[q].x;
            As[pb][(kv * 4 + 1) * GBM + lrow] = cva[q].y;
            As[pb][(kv * 4 + 2) * GBM + lrow] = cva[q].z;
            As[pb][(kv * 4 + 3) * GBM + lrow] = cva[q].w;
            Bs[pb][(kv * 4 + 0) * GBN + lrow] = cvb[q].x;
            Bs[pb][(kv * 4 + 1) * GBN + lrow] = cvb[q].y;
            Bs[pb][(kv * 4 + 2) * GBN + lrow] = cvb[q].z;
            Bs[pb][(kv * 4 + 3) * GBN + lrow] = cvb[q].w;
        }
        __syncthreads();
        if (kt + 1 < Ktiles) {
            #pragma unroll
            for (int q = 0; q < 2; ++q) {
                const int kg = (kt + 1) * GBK + (lkv0 + q) * 4;
                nva[q] = make_float4(0.f, 0.f, 0.f, 0.f);
                nvb[q] = make_float4(0.f, 0.f, 0.f, 0.f);
                if (kg + 3 < Kd) {
                    nva[q] = *(const float4*)(arow_p + kg);
                    if (bvalid) nvb[q] = *(const float4*)(brow_p + kg);
                }
            }
        }
        #pragma unroll
        for (int k = 0; k < GBK; ++k) {
            const float4 a0 = *(const float4*)&As[pb][k * GBM + ty * 4];
            const float4 a1 = *(const float4*)&As[pb][k * GBM + 64 + ty * 4];
            const ulonglong2 b0 = *(const ulonglong2*)&Bs[pb][k * GBN + tx * 4];
            const ulonglong2 b1 = *(const ulonglong2*)&Bs[pb][k * GBN + 64 + tx * 4];
            const ull bv2[4] = {b0.x, b0.y, b1.x, b1.y};
            const float av[8] = {a0.x, a0.y, a0.z, a0.w, a1.x, a1.y, a1.z, a1.w};
            #pragma unroll
            for (int i = 0; i < 8; ++i) {
                const ull av2 = pk2(av[i], av[i]);
                #pragma unroll
                for (int j = 0; j < 4; ++j)
                    acc2[i][j] = ffma2(av2, bv2[j], acc2[i][j]);
            }
        }
        #pragma unroll
        for (int q = 0; q < 2; ++q) { cva[q] = nva[q]; cvb[q] = nvb[q]; }
    }
    #pragma unroll
    for (int i = 0; i < 8; ++i) {
        const int mi = (i < 4) ? (ty * 4 + i) : (64 + ty * 4 + (i - 4));
        const int m  = m0 + mi;
        #pragma unroll
        for (int j = 0; j < 4; ++j) {
            const float2 v = unpk2(acc2[i][j]);
            const int c0 = (j < 2) ? (tx * 4 + 2 * j) : (64 + tx * 4 + 2 * (j - 2));
            const int n1 = n0 + c0, n2 = n0 + c0 + 1;
            if (XGI) {
                C[(size_t)m * N + n1] = v.x + bias[(n1 & 3) * 256 + (n1 >> 2)];
                C[(size_t)m * N + n2] = v.y + bias[(n2 & 3) * 256 + (n2 >> 2)];
            } else {
                if (n1 < N) C[(size_t)m * N + n1] = v.x + bias[n1];
                if (n2 < N) C[(size_t)m * N + n2] = v.y + bias[n2];
            }
        }
    }
}

// ---------------- persistent bidirectional LSTM scan: slice dataflow ----------------
// grid = 128 blocks = 2 dirs x 8 batch-groups x 8 unit-slices.
// CTA owns 8 batches x 32 units; Whh slice (128 rows x 256) in smem.
// matvec iteration q consumes exactly CTA us=q's h-slice:
//   - own slice (q=us): read from smem double-buffer (written at prior epilogue)
//   - peer slices: per-producer monotonic flag + __ldg, register double-buffered
//     so slice j+1's loads overlap slice j's FFMA2 block. ONE syncthreads/step.
#define LSTM_SMEM (2 * 8 * 8 * 16 + 128 * 264 * 4)   // hs[2][8][8] float4 + Ws[128][264]

__global__ void __launch_bounds__(256)
lstm_scan(const float* __restrict__ xgF, const float* __restrict__ xgBk,
          const float* __restrict__ WhhF, const float* __restrict__ WhhB,
          float* __restrict__ hout)
{
    extern __shared__ char sm_raw[];
    float4* hs4 = (float4*)sm_raw;                       // [2][8][8]
    float*  Ws  = (float*)(sm_raw + 2 * 8 * 8 * 16);     // [128][264]

    const int dir = blockIdx.x >> 6;
    const int loc = blockIdx.x & 63;
    const int bg  = loc >> 3;
    const int us  = loc & 7;
    const int b0  = bg * 8;
    const int u0  = us * 32;
    const int tid = threadIdx.x;
    const int ul  = tid >> 3;
    const int ks  = tid & 7;
    const int unit = u0 + ul;
    const int dof  = dir ? 256 : 0;
    const int bb   = b0 + ks;

    const float* xg  = dir ? xgBk : xgF;
    const float* Whh = dir ? WhhB : WhhF;
    unsigned* flg = g_bar + (dir * 8 + bg) * 8 * 32;     // slot j at flg[j*32]

    for (int i = tid; i < 128 * 256; i += 256) {
        const int r = i >> 8, k = i & 255;
        const int g = r >> 5, uu = r & 31;
        Ws[r * 264 + k] = Whh[(size_t)(g * 256 + u0 + uu) * 256 + k];
    }
    __syncthreads();

    const float4* wp0 = (const float4*)&Ws[(0 * 32 + ul) * 264];
    const float4* wp1 = (const float4*)&Ws[(1 * 32 + ul) * 264];
    const float4* wp2 = (const float4*)&Ws[(2 * 32 + ul) * 264];
    const float4* wp3 = (const float4*)&Ws[(3 * 32 + ul) * 264];

    float cc = 0.0f;
    int p = 0;

    for (int s = 0; s < TQ; ++s) {
        const int t = dir ? (TQ - 1 - s) : s;

        // xg prefetch: ONE float4 = 4 gate inputs for (bb, unit)
        const float4 xq = __ldg((const float4*)(xg + ((size_t)t * BQ + bb) * 1024 + (size_t)unit * 4));

        ull acc2[8][4];
        #pragma unroll
        for (int i = 0; i < 8; ++i)
            #pragma unroll
            for (int g = 0; g < 4; ++g) acc2[i][g] = 0ull;

        if (s > 0) {
            // prefetch peer flags (L2, bypass L1)
            unsigned f[8];
            #pragma unroll
            for (int j = 0; j < 8; ++j)
                f[j] = (j == us) ? 0xFFFFFFFFu : ldcg_u32(&flg[j * 32]);

            const int tp = dir ? (t + 1) : (t - 1);
            const float* hb = hout + ((size_t)tp * BQ + b0) * 512 + dof;

            // own slice from smem (produced by this CTA last step)
            ulonglong2 hcur[8];
            #pragma unroll
            for (int i = 0; i < 8; ++i)
                hcur[i] = *(const ulonglong2*)&hs4[(p * 8 + i) * 8 + ks];
            int qcur = us;

            #pragma unroll
            for (int jj = 0; jj < 8; ++jj) {
                ulonglong2 hnxt[8];
                int qn = 0;
                if (jj < 7) {
                    qn = us + 1 + jj; if (qn >= 8) qn -= 8;
                    unsigned v = f[qn];
                    while (v < (unsigned)s) v = ldacq_u32(&flg[qn * 32]);
                    const float* hq = hb + 4 * (ks + 8 * qn);
                    #pragma unroll
                    for (int i = 0; i < 8; ++i)
                        hnxt[i] = __ldg((const ulonglong2*)(hq + (size_t)i * 512));
                }
                // compute slice qcur (loads for qn already in flight)
                {
                    const int kv = ks + 8 * qcur;
                    const ulonglong2 w0 = *(const ulonglong2*)(wp0 + kv);
                    const ulonglong2 w1 = *(const ulonglong2*)(wp1 + kv);
                    const ulonglong2 w2 = *(const ulonglong2*)(wp2 + kv);
                    const ulonglong2 w3 = *(const ulonglong2*)(wp3 + kv);
                    #pragma unroll
                    for (int i = 0; i < 8; ++i) {
                        acc2[i][0] = ffma2(hcur[i].x, w0.x, acc2[i][0]);
                        acc2[i][0] = ffma2(hcur[i].y, w0.y, acc2[i][0]);
                        acc2[i][1] = ffma2(hcur[i].x, w1.x, acc2[i][1]);
                        acc2[i][1] = ffma2(hcur[i].y, w1.y, acc2[i][1]);
                        acc2[i][2] = ffma2(hcur[i].x, w2.x, acc2[i][2]);
                        acc2[i][2] = ffma2(hcur[i].y, w2.y, acc2[i][2]);
                        acc2[i][3] = ffma2(hcur[i].x, w3.x, acc2[i][3]);
                        acc2[i][3] = ffma2(hcur[i].y, w3.y, acc2[i][3]);
                    }
                }
                if (jj < 7) {
                    #pragma unroll
                    for (int i = 0; i < 8; ++i) hcur[i] = hnxt[i];
                    qcur = qn;
                }
            }
        }

        // ---- value-routed butterfly over ks lanes: lane ks ends owning batch ks ----
        float v8[8][4];
        #pragma unroll
        for (int i = 0; i < 8; ++i)
            #pragma unroll
            for (int g = 0; g < 4; ++g) {
                const float2 pr = unpk2(acc2[i][g]);
                v8[i][g] = pr.x + pr.y;
            }
        const bool q2 = (ks & 4) != 0;
        float v4[4][4];
        #pragma unroll
        for (int j = 0; j < 4; ++j)
            #pragma unroll
            for (int g = 0; g < 4; ++g) {
                const float snd = q2 ? v8[j][g] : v8[j + 4][g];
                const float got = __shfl_xor_sync(0xffffffffu, snd, 4);
                v4[j][g] = (q2 ? v8[j + 4][g] : v8[j][g]) + got;
            }
        const bool q1 = (ks & 2) != 0;
        float v2r[2][4];
        #pragma unroll
        for (int j = 0; j < 2; ++j)
            #pragma unroll
            for (int g = 0; g < 4; ++g) {
                const float snd = q1 ? v4[j][g] : v4[j + 2][g];
                const float got = __shfl_xor_sync(0xffffffffu, snd, 2);
                v2r[j][g] = (q1 ? v4[j + 2][g] : v4[j][g]) + got;
            }
        const bool q0 = (ks & 1) != 0;
        float z[4];
        #pragma unroll
        for (int g = 0; g < 4; ++g) {
            const float snd = q0 ? v2r[0][g] : v2r[1][g];
            const float got = __shfl_xor_sync(0xffffffffu, snd, 1);
            z[g] = (q0 ? v2r[1][g] : v2r[0][g]) + got;
        }

        // ---- fully parallel epilogue: one LSTM cell per thread ----
        {
            const float zi = z[0] + xq.x;
            const float zf = z[1] + xq.y;
            const float zg = z[2] + xq.z;
            const float zo = z[3] + xq.w;
            const float ig = sigf(zi), fg = sigf(zf), gg = tanh_f(zg), og = sigf(zo);
            cc = fg * cc + ig * gg;
            const float hval = og * tanh_f(cc);
            hout[((size_t)t * BQ + bb) * 512 + dof + unit] = hval;
            // own-slice smem for next step: hs4[p^1][batch=ks][float4 ul>>2].comp[ul&3]
            ((float*)&hs4[((p ^ 1) * 8 + ks) * 8 + (ul >> 2)])[ul & 3] = hval;
        }

        __syncthreads();          // publish hs + order all threads' hout stores
        if (tid == 0) {
            asm volatile("st.release.gpu.global.u32 [%0], %1;"
                         :: "l"(&flg[us * 32]), "r"((unsigned)(s + 1)) : "memory");
        }
        p ^= 1;
    }
}

// ---------------- CRF: one block per batch ----------------
__global__ void __launch_bounds__(64)
crf_kernel(const int* __restrict__ text, const int* __restrict__ sbj,
           const float* __restrict__ em, const float* __restrict__ start_t,
           const float* __restrict__ end_t, const float* __restrict__ trans,
           float* __restrict__ llh)
{
    const int b   = blockIdx.x;
    const int tid = threadIdx.x;
    __shared__ float tr[KQ * KQ];
    __shared__ float sc[KQ];
    for (int i = tid; i < KQ * KQ; i += 64) tr[i] = trans[i];
    if (tid < KQ) sc[tid] = start_t[tid] + em[(size_t)b * KQ + tid];
    __syncthreads();

    for (int t = 1; t < TQ; ++t) {
        const int tok = text[b * TQ + t];
        if (tok != 0) {
            float nv = 0.0f;
            if (tid < KQ) {
                float mx = -1e30f;
                #pragma unroll 1
                for (int j = 0; j < KQ; ++j) mx = fmaxf(mx, sc[j] + tr[j * KQ + tid]);
                float ssum = 0.0f;
                #pragma unroll 1
                for (int j = 0; j < KQ; ++j) ssum += __expf(sc[j] + tr[j * KQ + tid] - mx);
                nv = em[((size_t)t * BQ + b) * KQ + tid] + mx + __logf(ssum);
            }
            __syncthreads();
            if (tid < KQ) sc[tid] = nv;
            __syncthreads();
        }
    }

    if (tid == 0) {
        float mx = -1e30f;
        for (int k = 0; k < KQ; ++k) mx = fmaxf(mx, sc[k] + end_t[k]);
        float ssum = 0.0f;
        for (int k = 0; k < KQ; ++k) ssum += __expf(sc[k] + end_t[k] - mx);
        const float logZ = mx + __logf(ssum);
        int tag0 = sbj[b * TQ + 0];
        float num = start_t[tag0] + em[(size_t)b * KQ + tag0];
        int prev = tag0, last = tag0;
        for (int t = 1; t < TQ; ++t) {
            if (text[b * TQ + t] != 0) {
                const int tg = sbj[b * TQ + t];
                num += em[((size_t)t * BQ + b) * KQ + tg] + tr[prev * KQ + tg];
                prev = tg; last = tg;
            }
        }
        num += end_t[last];
        llh[b] = num - logZ;
    }
}

// ---------------- finalize ----------------
__global__ void __launch_bounds__(256)
finalize_kernel(const int* __restrict__ text, const float* __restrict__ llh,
                float* __restrict__ out)
{
    __shared__ float sred[256];
    __shared__ float cred[256];
    const int tid = threadIdx.x;
    float s = 0.0f, c = 0.0f;
    for (int i = tid; i < BQ; i += 256) s += llh[i];
    for (int i = tid; i < BQ * TQ; i += 256) c += (text[i] != 0) ? 1.0f : 0.0f;
    sred[tid] = s; cred[tid] = c;
    __syncthreads();
    for (int off = 128; off > 0; off >>= 1) {
        if (tid < off) { sred[tid] += sred[tid + off]; cred[tid] += cred[tid + off]; }
        __syncthreads();
    }
    if (tid == 0) out[0] = -(sred[0] / cred[0]);
}

// ---------------- launch ----------------
extern "C" void kernel_launch(void* const* d_in, const int* in_sizes, int n_in,
                              void* d_out, int out_size)
{
    const int*   text  = (const int*)  d_in[0];
    const int*   sbj   = (const int*)  d_in[1];
    const float* emb   = (const float*)d_in[2];
    const float* Wih0f = (const float*)d_in[3];
    const float* Whh0f = (const float*)d_in[4];
    const float* b0f   = (const float*)d_in[5];
    const float* Wih0b = (const float*)d_in[6];
    const float* Whh0b = (const float*)d_in[7];
    const float* b0b   = (const float*)d_in[8];
    const float* Wih1f = (const float*)d_in[9];
    const float* Whh1f = (const float*)d_in[10];
    const float* b1f   = (const float*)d_in[11];
    const float* Wih1b = (const float*)d_in[12];
    const float* Whh1b = (const float*)d_in[13];
    const float* b1b   = (const float*)d_in[14];
    const float* W_sbj = (const float*)d_in[15];
    const float* b_sbj = (const float*)d_in[16];
    const float* st_t  = (const float*)d_in[17];
    const float* en_t  = (const float*)d_in[18];
    const float* trans = (const float*)d_in[19];
    float* out = (float*)d_out;

    float *xgA, *xgB, *h0, *h1, *em, *llh;
    cudaGetSymbolAddress((void**)&xgA, g_xgA);
    cudaGetSymbolAddress((void**)&xgB, g_xgB);
    cudaGetSymbolAddress((void**)&h0,  g_h0);
    cudaGetSymbolAddress((void**)&h1,  g_h1);
    cudaGetSymbolAddress((void**)&em,  g_em);
    cudaGetSymbolAddress((void**)&llh, g_llh);

    cudaFuncSetAttribute(lstm_scan, cudaFuncAttributeMaxDynamicSharedMemorySize, LSTM_SMEM);

    const dim3 gGemmFull(1024 / GBN, MBQ / GBM);   // (8, 128)
    const dim3 gGemmEm(1, MBQ / GBM);              // (1, 128)  N=37

    gemm_nt_bias<true, true><<<gGemmFull, 256>>>(emb, text, Wih0f, b0f, xgA, MBQ, 1024, DQ, DQ);
    gemm_nt_bias<true, true><<<gGemmFull, 256>>>(emb, text, Wih0b, b0b, xgB, MBQ, 1024, DQ, DQ);
    reset_bar_kernel<<<1, 256>>>();
    lstm_scan<<<128, 256, LSTM_SMEM>>>(xgA, xgB, Whh0f, Whh0b, h0);

    gemm_nt_bias<false, true><<<gGemmFull, 256>>>(h0, nullptr, Wih1f, b1f, xgA, MBQ, 1024, 512, 512);
    gemm_nt_bias<false, true><<<gGemmFull, 256>>>(h0, nullptr, Wih1b, b1b, xgB, MBQ, 1024, 512, 512);
    reset_bar_kernel<<<1, 256>>>();
    lstm_scan<<<128, 256, LSTM_SMEM>>>(xgA, xgB, Whh1f, Whh1b, h1);

    gemm_nt_bias<false, false><<<gGemmEm, 256>>>(h1, nullptr, W_sbj, b_sbj, em, MBQ, KQ, 512, 512);

    crf_kernel<<<BQ, 64>>>(text, sbj, em, st_t, en_t, trans, llh);
    finalize_kernel<<<1, 256>>>(text, llh, out);
}

// round 17
// speedup vs baseline: 1.0613x; 1.0613x over previous
#include <cuda_runtime.h>
#include <cstdint>

// Problem dims (fixed for this instance)
#define BQ 64
#define TQ 256
#define DQ 300
#define HQ 256      // hidden
#define KQ 37       // tags
#define MBQ (TQ*BQ) // 16384 rows (t*B + b)

typedef unsigned long long ull;

// ---------------- scratch (static device globals; no allocation) ----------------
__device__ float g_xgA[(size_t)MBQ * 1024];  // 64 MB (gate-interleaved [t][b][unit][gate])
__device__ float g_xgB[(size_t)MBQ * 1024];  // 64 MB
__device__ float g_h0 [(size_t)MBQ * 512];   // 32 MB
__device__ float g_h1 [(size_t)MBQ * 512];   // 32 MB
__device__ float g_em [(size_t)MBQ * KQ];    // 2.4 MB
__device__ float g_llh[BQ];
__device__ unsigned g_bar[512];              // 16 used counters, padded 128B apart

// ---------------- helpers ----------------
__device__ __forceinline__ float sigf(float x)   { return 1.0f / (1.0f + __expf(-x)); }
__device__ __forceinline__ float tanh_f(float x) { return 2.0f / (1.0f + __expf(-2.0f * x)) - 1.0f; }

__device__ __forceinline__ ull ffma2(ull a, ull b, ull c) {
    ull d;
    asm("fma.rn.f32x2 %0, %1, %2, %3;" : "=l"(d) : "l"(a), "l"(b), "l"(c));
    return d;
}
__device__ __forceinline__ ull pk2(float lo, float hi) {
    ull r;
    asm("mov.b64 %0, {%1, %2};" : "=l"(r) : "f"(lo), "f"(hi));
    return r;
}
__device__ __forceinline__ float2 unpk2(ull v) {
    float2 r;
    asm("mov.b64 {%0, %1}, %2;" : "=f"(r.x), "=f"(r.y) : "l"(v));
    return r;
}

__global__ void reset_bar_kernel() {
    if (threadIdx.x < 512) g_bar[threadIdx.x] = 0u;
}

// ---------------- GEMM: C[M,P] = A(M,K) * Bw'(P,K)^T + bias' ----------------
// 128x128 tile, 16-k, 256 threads, 8x8 microtile via FFMA2, reg prefetch,
// double-buffered smem (ONE sync per k-tile).
// XGI: logical output column p maps to weight/bias row (p&3)*256 + (p>>2).
#define GBM 128
#define GBN 128
#define GBK 16

template <bool GATHER, bool XGI>
__global__ void __launch_bounds__(256)
gemm_nt_bias(const float* __restrict__ A, const int* __restrict__ textp,
             const float* __restrict__ Bw, const float* __restrict__ bias,
             float* __restrict__ C, int M, int N, int Kd, int lda)
{
    __shared__ float As[2][GBK * GBM];
    __shared__ float Bs[2][GBK * GBN];

    const int tid = threadIdx.x;
    const int m0  = blockIdx.y * GBM;
    const int n0  = blockIdx.x * GBN;
    const int tx  = tid & 15;
    const int ty  = tid >> 4;
    const int lrow = tid >> 1;
    const int lkv0 = (tid & 1) * 2;

    ull acc2[8][4];
    #pragma unroll
    for (int i = 0; i < 8; ++i)
        #pragma unroll
        for (int j = 0; j < 4; ++j) acc2[i][j] = 0ull;

    const float* arow_p;
    {
        const int m = m0 + lrow;
        if (GATHER) {
            const int bb = m & 63;
            const int tt = m >> 6;
            const int tok = textp[bb * TQ + tt];
            arow_p = A + (size_t)tok * lda;
        } else {
            arow_p = A + (size_t)m * lda;
        }
    }
    const int ncol = n0 + lrow;
    const int brow = XGI ? ((ncol & 3) * 256 + (ncol >> 2)) : ncol;
    const float* brow_p = Bw + (size_t)brow * Kd;
    const bool bvalid = ncol < N;

    const int Ktiles = (Kd + GBK - 1) / GBK;

    float4 cva[2], cvb[2], nva[2], nvb[2];
    #pragma unroll
    for (int q = 0; q < 2; ++q) {
        const int kg = (lkv0 + q) * 4;
        cva[q] = make_float4(0.f, 0.f, 0.f, 0.f);
        cvb[q] = make_float4(0.f, 0.f, 0.f, 0.f);
        if (kg + 3 < Kd) {
            cva[q] = *(const float4*)(arow_p + kg);
            if (bvalid) cvb[q] = *(const float4*)(brow_p + kg);
        }
    }

    for (int kt = 0; kt < Ktiles; ++kt) {
        const int pb = kt & 1;
        #pragma unroll
        for (int q = 0; q < 2; ++q) {
            const int kv = lkv0 + q;
            As[pb][(kv * 4 + 0) * GBM + lrow] = cva[q].x;
            As[pb][(kv * 4 + 1) * GBM + lrow] = cva[q].y;
            As[pb][(kv * 4 + 2) * GBM + lrow] = cva[q].z;
            As[pb][(kv * 4 + 3) * GBM + lrow] = cva[q].w;
            Bs[pb][(kv * 4 + 0) * GBN + lrow] = cvb[q].x;
            Bs[pb][(kv * 4 + 1) * GBN + lrow] = cvb[q].y;
            Bs[pb][(kv * 4 + 2) * GBN + lrow] = cvb[q].z;
            Bs[pb][(kv * 4 + 3) * GBN + lrow] = cvb[q].w;
        }
        __syncthreads();
        if (kt + 1 < Ktiles) {
            #pragma unroll
            for (int q = 0; q < 2; ++q) {
                const int kg = (kt + 1) * GBK + (lkv0 + q) * 4;
                nva[q] = make_float4(0.f, 0.f, 0.f, 0.f);
                nvb[q] = make_float4(0.f, 0.f, 0.f, 0.f);
                if (kg + 3 < Kd) {
                    nva[q] = *(const float4*)(arow_p + kg);
                    if (bvalid) nvb[q] = *(const float4*)(brow_p + kg);
                }
            }
        }
        #pragma unroll
        for (int k = 0; k < GBK; ++k) {
            const float4 a0 = *(const float4*)&As[pb][k * GBM + ty * 4];
            const float4 a1 = *(const float4*)&As[pb][k * GBM + 64 + ty * 4];
            const ulonglong2 b0 = *(const ulonglong2*)&Bs[pb][k * GBN + tx * 4];
            const ulonglong2 b1 = *(const ulonglong2*)&Bs[pb][k * GBN + 64 + tx * 4];
            const ull bv2[4] = {b0.x, b0.y, b1.x, b1.y};
            const float av[8] = {a0.x, a0.y, a0.z, a0.w, a1.x, a1.y, a1.z, a1.w};
            #pragma unroll
            for (int i = 0; i < 8; ++i) {
                const ull av2 = pk2(av[i], av[i]);
                #pragma unroll
                for (int j = 0; j < 4; ++j)
                    acc2[i][j] = ffma2(av2, bv2[j], acc2[i][j]);
            }
        }
        #pragma unroll
        for (int q = 0; q < 2; ++q) { cva[q] = nva[q]; cvb[q] = nvb[q]; }
    }
    #pragma unroll
    for (int i = 0; i < 8; ++i) {
        const int mi = (i < 4) ? (ty * 4 + i) : (64 + ty * 4 + (i - 4));
        const int m  = m0 + mi;
        #pragma unroll
        for (int j = 0; j < 4; ++j) {
            const float2 v = unpk2(acc2[i][j]);
            const int c0 = (j < 2) ? (tx * 4 + 2 * j) : (64 + tx * 4 + 2 * (j - 2));
            const int n1 = n0 + c0, n2 = n0 + c0 + 1;
            if (XGI) {
                C[(size_t)m * N + n1] = v.x + bias[(n1 & 3) * 256 + (n1 >> 2)];
                C[(size_t)m * N + n2] = v.y + bias[(n2 & 3) * 256 + (n2 >> 2)];
            } else {
                if (n1 < N) C[(size_t)m * N + n1] = v.x + bias[n1];
                if (n2 < N) C[(size_t)m * N + n2] = v.y + bias[n2];
            }
        }
    }
}

// ---------------- persistent bidirectional LSTM scan ----------------
// grid = 128 blocks = 2 dirs x 8 batch-groups x 8 unit-slices; 512 THREADS.
// CTA owns 8 batches x 32 units; Whh slice (128 rows x 256) in smem.
// Thread map: ul=tid>>4 (local unit 0..31), ks=tid&15 (16-way k-slice).
// Each thread: k-quarter kv=ks+16q (q=0..3), all 8 batches. Butterfly over 16
// lanes (xor 8,4,2 route batches, xor 1 completes the sum); lane pair (ks,ks^1)
// duplicates cell (batch=ks>>1, unit) deterministically; even lane stores h.
// Barrier: single atomic counter per (dir, batch-group), release/acquire.
#define LSTM_SMEM (8 * 65 * 16 + 128 * 264 * 4)   // hs float4[8][65] + Ws[128][264]

__global__ void __launch_bounds__(512)
lstm_scan(const float* __restrict__ xgF, const float* __restrict__ xgBk,
          const float* __restrict__ WhhF, const float* __restrict__ WhhB,
          float* __restrict__ hout)
{
    extern __shared__ char sm_raw[];
    float4* hs = (float4*)sm_raw;                    // [8][65]
    float*  Ws = (float*)(sm_raw + 8 * 65 * 16);     // [128][264]

    const int dir = blockIdx.x >> 6;
    const int loc = blockIdx.x & 63;
    const int bg  = loc >> 3;
    const int us  = loc & 7;
    const int b0  = bg * 8;
    const int u0  = us * 32;
    const int tid = threadIdx.x;
    const int ul  = tid >> 4;         // local unit 0..31
    const int ks  = tid & 15;         // 16-way k-slice
    const int unit = u0 + ul;
    const int dof  = dir ? 256 : 0;
    const int bb   = b0 + (ks >> 1);  // this thread's epilogue batch (lane pair dup)

    const float* xg  = dir ? xgBk : xgF;
    const float* Whh = dir ? WhhB : WhhF;
    unsigned* bar = &g_bar[(dir * 8 + bg) * 32];

    for (int i = tid; i < 128 * 256; i += 512) {
        const int r = i >> 8, k = i & 255;
        const int g = r >> 5, uu = r & 31;
        Ws[r * 264 + k] = Whh[(size_t)(g * 256 + u0 + uu) * 256 + k];
    }
    __syncthreads();

    const float4* wp0 = (const float4*)&Ws[(0 * 32 + ul) * 264];
    const float4* wp1 = (const float4*)&Ws[(1 * 32 + ul) * 264];
    const float4* wp2 = (const float4*)&Ws[(2 * 32 + ul) * 264];
    const float4* wp3 = (const float4*)&Ws[(3 * 32 + ul) * 264];

    float cc = 0.0f;

    for (int s = 0; s < TQ; ++s) {
        const int t = dir ? (TQ - 1 - s) : s;

        // xg prefetch: ONE float4 = 4 gate inputs for (bb, unit)
        const float4 xq = __ldg((const float4*)(xg + ((size_t)t * BQ + bb) * 1024 + (size_t)unit * 4));

        ull acc2[8][4];
        #pragma unroll
        for (int i = 0; i < 8; ++i)
            #pragma unroll
            for (int g = 0; g < 4; ++g) acc2[i][g] = 0ull;

        if (s > 0) {
            // stage h_prev for OUR 8 batches (this direction) into smem, coalesced
            const int tp = dir ? (t + 1) : (t - 1);
            const float* hb = hout + ((size_t)tp * BQ + b0) * 512 + dof;
            {
                const int b = tid >> 6, kv = tid & 63;   // exactly 512 float4s
                hs[b * 65 + kv] = __ldg((const float4*)(hb + (size_t)b * 512 + kv * 4));
            }
            __syncthreads();
            // mat-vec from smem: this thread's k-quarter
            #pragma unroll
            for (int q = 0; q < 4; ++q) {
                const int kv = ks + q * 16;
                const ulonglong2 w0 = *(const ulonglong2*)(wp0 + kv);
                const ulonglong2 w1 = *(const ulonglong2*)(wp1 + kv);
                const ulonglong2 w2 = *(const ulonglong2*)(wp2 + kv);
                const ulonglong2 w3 = *(const ulonglong2*)(wp3 + kv);
                #pragma unroll
                for (int i = 0; i < 8; ++i) {
                    const ulonglong2 h2 = *(const ulonglong2*)&hs[i * 65 + kv];
                    acc2[i][0] = ffma2(h2.x, w0.x, acc2[i][0]);
                    acc2[i][0] = ffma2(h2.y, w0.y, acc2[i][0]);
                    acc2[i][1] = ffma2(h2.x, w1.x, acc2[i][1]);
                    acc2[i][1] = ffma2(h2.y, w1.y, acc2[i][1]);
                    acc2[i][2] = ffma2(h2.x, w2.x, acc2[i][2]);
                    acc2[i][2] = ffma2(h2.y, w2.y, acc2[i][2]);
                    acc2[i][3] = ffma2(h2.x, w3.x, acc2[i][3]);
                    acc2[i][3] = ffma2(h2.y, w3.y, acc2[i][3]);
                }
            }
        }

        // ---- value-routed butterfly over 16 ks lanes ----
        float v8[8][4];
        #pragma unroll
        for (int i = 0; i < 8; ++i)
            #pragma unroll
            for (int g = 0; g < 4; ++g) {
                const float2 p = unpk2(acc2[i][g]);
                v8[i][g] = p.x + p.y;
            }
        const bool b3 = (ks & 8) != 0;    // keep batches b3*4 + j
        float v4[4][4];
        #pragma unroll
        for (int j = 0; j < 4; ++j)
            #pragma unroll
            for (int g = 0; g < 4; ++g) {
                const float snd = b3 ? v8[j][g] : v8[j + 4][g];
                const float got = __shfl_xor_sync(0xffffffffu, snd, 8);
                v4[j][g] = (b3 ? v8[j + 4][g] : v8[j][g]) + got;
            }
        const bool b2f = (ks & 4) != 0;   // keep batches b3*4 + b2f*2 + j
        float v2[2][4];
        #pragma unroll
        for (int j = 0; j < 2; ++j)
            #pragma unroll
            for (int g = 0; g < 4; ++g) {
                const float snd = b2f ? v4[j][g] : v4[j + 2][g];
                const float got = __shfl_xor_sync(0xffffffffu, snd, 4);
                v2[j][g] = (b2f ? v4[j + 2][g] : v4[j][g]) + got;
            }
        const bool b1f = (ks & 2) != 0;   // keep batch ks>>1
        float z0[4];
        #pragma unroll
        for (int g = 0; g < 4; ++g) {
            const float snd = b1f ? v2[0][g] : v2[1][g];
            const float got = __shfl_xor_sync(0xffffffffu, snd, 2);
            z0[g] = (b1f ? v2[1][g] : v2[0][g]) + got;
        }
        float z[4];
        #pragma unroll
        for (int g = 0; g < 4; ++g)       // final k-halves reduction (lane pair dup)
            z[g] = z0[g] + __shfl_xor_sync(0xffffffffu, z0[g], 1);

        // ---- epilogue: one LSTM cell per lane pair (deterministic duplicate) ----
        {
            const float zi = z[0] + xq.x;
            const float zf = z[1] + xq.y;
            const float zg = z[2] + xq.z;
            const float zo = z[3] + xq.w;
            const float ig = sigf(zi), fg = sigf(zf), gg = tanh_f(zg), og = sigf(zo);
            cc = fg * cc + ig * gg;
            if ((ks & 1) == 0)
                hout[((size_t)t * BQ + bb) * 512 + dof + unit] = og * tanh_f(cc);
        }

        // ---- inter-CTA step barrier: single counter, release/acquire ----
        if (s + 1 < TQ) {
            __syncthreads();
            if (tid == 0) {
                asm volatile("red.release.gpu.global.add.u32 [%0], %1;"
                             :: "l"(bar), "r"(1u) : "memory");
                const unsigned target = (unsigned)(s + 1) * 8u;
                unsigned v;
                do {
                    asm volatile("ld.acquire.gpu.global.u32 %0, [%1];"
                                 : "=r"(v) : "l"(bar) : "memory");
                } while (v < target);
            }
            __syncthreads();
        }
    }
}

// ---------------- CRF: one block per batch ----------------
__global__ void __launch_bounds__(64)
crf_kernel(const int* __restrict__ text, const int* __restrict__ sbj,
           const float* __restrict__ em, const float* __restrict__ start_t,
           const float* __restrict__ end_t, const float* __restrict__ trans,
           float* __restrict__ llh)
{
    const int b   = blockIdx.x;
    const int tid = threadIdx.x;
    __shared__ float tr[KQ * KQ];
    __shared__ float sc[KQ];
    for (int i = tid; i < KQ * KQ; i += 64) tr[i] = trans[i];
    if (tid < KQ) sc[tid] = start_t[tid] + em[(size_t)b * KQ + tid];
    __syncthreads();

    for (int t = 1; t < TQ; ++t) {
        const int tok = text[b * TQ + t];
        if (tok != 0) {
            float nv = 0.0f;
            if (tid < KQ) {
                float mx = -1e30f;
                #pragma unroll 1
                for (int j = 0; j < KQ; ++j) mx = fmaxf(mx, sc[j] + tr[j * KQ + tid]);
                float ssum = 0.0f;
                #pragma unroll 1
                for (int j = 0; j < KQ; ++j) ssum += __expf(sc[j] + tr[j * KQ + tid] - mx);
                nv = em[((size_t)t * BQ + b) * KQ + tid] + mx + __logf(ssum);
            }
            __syncthreads();
            if (tid < KQ) sc[tid] = nv;
            __syncthreads();
        }
    }

    if (tid == 0) {
        float mx = -1e30f;
        for (int k = 0; k < KQ; ++k) mx = fmaxf(mx, sc[k] + end_t[k]);
        float ssum = 0.0f;
        for (int k = 0; k < KQ; ++k) ssum += __expf(sc[k] + end_t[k] - mx);
        const float logZ = mx + __logf(ssum);
        int tag0 = sbj[b * TQ + 0];
        float num = start_t[tag0] + em[(size_t)b * KQ + tag0];
        int prev = tag0, last = tag0;
        for (int t = 1; t < TQ; ++t) {
            if (text[b * TQ + t] != 0) {
                const int tg = sbj[b * TQ + t];
                num += em[((size_t)t * BQ + b) * KQ + tg] + tr[prev * KQ + tg];
                prev = tg; last = tg;
            }
        }
        num += end_t[last];
        llh[b] = num - logZ;
    }
}

// ---------------- finalize ----------------
__global__ void __launch_bounds__(256)
finalize_kernel(const int* __restrict__ text, const float* __restrict__ llh,
                float* __restrict__ out)
{
    __shared__ float sred[256];
    __shared__ float cred[256];
    const int tid = threadIdx.x;
    float s = 0.0f, c = 0.0f;
    for (int i = tid; i < BQ; i += 256) s += llh[i];
    for (int i = tid; i < BQ * TQ; i += 256) c += (text[i] != 0) ? 1.0f : 0.0f;
    sred[tid] = s; cred[tid] = c;
    __syncthreads();
    for (int off = 128; off > 0; off >>= 1) {
        if (tid < off) { sred[tid] += sred[tid + off]; cred[tid] += cred[tid + off]; }
        __syncthreads();
    }
    if (tid == 0) out[0] = -(sred[0] / cred[0]);
}

// ---------------- launch ----------------
extern "C" void kernel_launch(void* const* d_in, const int* in_sizes, int n_in,
                              void* d_out, int out_size)
{
    const int*   text  = (const int*)  d_in[0];
    const int*   sbj   = (const int*)  d_in[1];
    const float* emb   = (const float*)d_in[2];
    const float* Wih0f = (const float*)d_in[3];
    const float* Whh0f = (const float*)d_in[4];
    const float* b0f   = (const float*)d_in[5];
    const float* Wih0b = (const float*)d_in[6];
    const float* Whh0b = (const float*)d_in[7];
    const float* b0b   = (const float*)d_in[8];
    const float* Wih1f = (const float*)d_in[9];
    const float* Whh1f = (const float*)d_in[10];
    const float* b1f   = (const float*)d_in[11];
    const float* Wih1b = (const float*)d_in[12];
    const float* Whh1b = (const float*)d_in[13];
    const float* b1b   = (const float*)d_in[14];
    const float* W_sbj = (const float*)d_in[15];
    const float* b_sbj = (const float*)d_in[16];
    const float* st_t  = (const float*)d_in[17];
    const float* en_t  = (const float*)d_in[18];
    const float* trans = (const float*)d_in[19];
    float* out = (float*)d_out;

    float *xgA, *xgB, *h0, *h1, *em, *llh;
    cudaGetSymbolAddress((void**)&xgA, g_xgA);
    cudaGetSymbolAddress((void**)&xgB, g_xgB);
    cudaGetSymbolAddress((void**)&h0,  g_h0);
    cudaGetSymbolAddress((void**)&h1,  g_h1);
    cudaGetSymbolAddress((void**)&em,  g_em);
    cudaGetSymbolAddress((void**)&llh, g_llh);

    cudaFuncSetAttribute(lstm_scan, cudaFuncAttributeMaxDynamicSharedMemorySize, LSTM_SMEM);

    const dim3 gGemmFull(1024 / GBN, MBQ / GBM);   // (8, 128)
    const dim3 gGemmEm(1, MBQ / GBM);              // (1, 128)  N=37

    gemm_nt_bias<true, true><<<gGemmFull, 256>>>(emb, text, Wih0f, b0f, xgA, MBQ, 1024, DQ, DQ);
    gemm_nt_bias<true, true><<<gGemmFull, 256>>>(emb, text, Wih0b, b0b, xgB, MBQ, 1024, DQ, DQ);
    reset_bar_kernel<<<1, 512>>>();
    lstm_scan<<<128, 512, LSTM_SMEM>>>(xgA, xgB, Whh0f, Whh0b, h0);

    gemm_nt_bias<false, true><<<gGemmFull, 256>>>(h0, nullptr, Wih1f, b1f, xgA, MBQ, 1024, 512, 512);
    gemm_nt_bias<false, true><<<gGemmFull, 256>>>(h0, nullptr, Wih1b, b1b, xgB, MBQ, 1024, 512, 512);
    reset_bar_kernel<<<1, 512>>>();
    lstm_scan<<<128, 512, LSTM_SMEM>>>(xgA, xgB, Whh1f, Whh1b, h1);

    gemm_nt_bias<false, false><<<gGemmEm, 256>>>(h1, nullptr, W_sbj, b_sbj, em, MBQ, KQ, 512, 512);

    crf_kernel<<<BQ, 64>>>(text, sbj, em, st_t, en_t, trans, llh);
    finalize_kernel<<<1, 256>>>(text, llh, out);
}